// round 4
// baseline (speedup 1.0000x reference)
#include <cuda_runtime.h>

#define NPTS 6144
#define NITERS 10

// Scratch (static device globals — allocation-free per harness rules)
__device__ unsigned char d_M[(size_t)NPTS * NPTS];   // 37.7 MB u8 matrix, L2-resident
__device__ float d_v0[NPTS];
__device__ float d_v1[NPTS];

__device__ __forceinline__ float fsqrt_approx(float x) {
    float r;
    asm("sqrt.approx.f32 %0, %1;" : "=f"(r) : "f"(x));
    return r;
}

// ---- packed f32x2 helpers (sm_103a) ----
typedef unsigned long long u64t;
__device__ __forceinline__ u64t pk2(float lo, float hi) {
    u64t r; asm("mov.b64 %0, {%1, %2};" : "=l"(r) : "f"(lo), "f"(hi)); return r;
}
__device__ __forceinline__ void upk2(float& lo, float& hi, u64t v) {
    asm("mov.b64 {%0, %1}, %2;" : "=f"(lo), "=f"(hi) : "l"(v));
}
__device__ __forceinline__ u64t add2(u64t a, u64t b) {
    u64t r; asm("add.rn.f32x2 %0, %1, %2;" : "=l"(r) : "l"(a), "l"(b)); return r;
}
__device__ __forceinline__ u64t mul2(u64t a, u64t b) {
    u64t r; asm("mul.rn.f32x2 %0, %1, %2;" : "=l"(r) : "l"(a), "l"(b)); return r;
}
__device__ __forceinline__ u64t fma2(u64t a, u64t b, u64t c) {
    u64t r; asm("fma.rn.f32x2 %0, %1, %2, %3;" : "=l"(r) : "l"(a), "l"(b), "l"(c));
    return r;
}

__global__ void k_init() {
    int i = blockIdx.x * blockDim.x + threadIdx.x;
    if (i < NPTS) d_v0[i] = 1.0f;
}

// Build M in u8 fixed-point: q = round(255 * max(0, 1 - 100*cross^2)),
// cross^2 = a + b - 2*sqrt(a*b), a=|p2_i-p2_j|^2, b=|p3_i-p3_j|^2.
// FMA chain runs packed 2-columns-wide via fma.rn.f32x2 (FFMA2);
// rounding via 2^23 magic add fused into the last packed FMA.
__global__ void __launch_bounds__(256) k_build(const float* __restrict__ p2,
                                               const float* __restrict__ p3) {
    const int tid = threadIdx.x;
    const int j0 = (blockIdx.x * 256 + tid) * 8;   // 8 cols
    const int r0 = blockIdx.y * 8;                 // 8 rows

    const float4* p2v = reinterpret_cast<const float4*>(p2);
    const float4* p3v = reinterpret_cast<const float4*>(p3);

    // column points, packed as negated pairs (sub -> add)
    u64t ncx[4], ncy[4], n3x[4], n3y[4], n3z[4];
#pragma unroll
    for (int k = 0; k < 4; k++) {
        float4 a = __ldg(&p2v[j0 / 2 + k]);
        ncx[k] = pk2(-a.x, -a.z);
        ncy[k] = pk2(-a.y, -a.w);
    }
    {
        float q3[24];
#pragma unroll
        for (int k = 0; k < 6; k++) {
            float4 a = __ldg(&p3v[(3 * j0) / 4 + k]);
            q3[4*k] = a.x; q3[4*k+1] = a.y; q3[4*k+2] = a.z; q3[4*k+3] = a.w;
        }
#pragma unroll
        for (int k = 0; k < 4; k++) {
            n3x[k] = pk2(-q3[6*k],   -q3[6*k+3]);
            n3y[k] = pk2(-q3[6*k+1], -q3[6*k+4]);
            n3z[k] = pk2(-q3[6*k+2], -q3[6*k+5]);
        }
    }
    // row points (uniform across block -> L1 broadcast)
    float rx[8], ry[8];
#pragma unroll
    for (int k = 0; k < 4; k++) {
        float4 a = __ldg(&p2v[r0 / 2 + k]);
        rx[2*k] = a.x; ry[2*k] = a.y; rx[2*k+1] = a.z; ry[2*k+1] = a.w;
    }
    float r3[24];
#pragma unroll
    for (int k = 0; k < 6; k++) {
        float4 a = __ldg(&p3v[(3 * r0) / 4 + k]);
        r3[4*k] = a.x; r3[4*k+1] = a.y; r3[4*k+2] = a.z; r3[4*k+3] = a.w;
    }

    const u64t NEG2  = pk2(-2.0f, -2.0f);
    const u64t NEGK  = pk2(-25500.0f, -25500.0f);
    const u64t MAGIC = pk2(8388863.0f, 8388863.0f);

#pragma unroll
    for (int r = 0; r < 8; r++) {
        const u64t sx2 = pk2(rx[r], rx[r]);
        const u64t sy2 = pk2(ry[r], ry[r]);
        const u64t sx3 = pk2(r3[3*r],   r3[3*r]);
        const u64t sy3 = pk2(r3[3*r+1], r3[3*r+1]);
        const u64t sz3 = pk2(r3[3*r+2], r3[3*r+2]);
        unsigned u[8];
#pragma unroll
        for (int p = 0; p < 4; p++) {
            u64t dx = add2(sx2, ncx[p]);
            u64t dy = add2(sy2, ncy[p]);
            u64t a  = fma2(dx, dx, mul2(dy, dy));
            u64t d0 = add2(sx3, n3x[p]);
            u64t d1 = add2(sy3, n3y[p]);
            u64t d2 = add2(sz3, n3z[p]);
            u64t b  = fma2(d2, d2, fma2(d1, d1, mul2(d0, d0)));
            u64t ab = mul2(a, b);
            u64t apb = add2(a, b);
            float ab0, ab1;
            upk2(ab0, ab1, ab);
            u64t s  = pk2(fsqrt_approx(ab0), fsqrt_approx(ab1));
            u64t cr = fma2(NEG2, s, apb);       // (sqrt a - sqrt b)^2
            u64t t  = fma2(NEGK, cr, MAGIC);    // 2^23 + 255 - 25500*cr
            float t0, t1;
            upk2(t0, t1, t);
            t0 = fminf(fmaxf(t0, 8388608.0f), 8388863.0f);
            t1 = fminf(fmaxf(t1, 8388608.0f), 8388863.0f);
            u[2*p]   = __float_as_uint(t0);     // byte = low 8 mantissa bits
            u[2*p+1] = __float_as_uint(t1);
        }
        unsigned w0 = __byte_perm(__byte_perm(u[0], u[1], 0x0040),
                                  __byte_perm(u[2], u[3], 0x0040), 0x5410);
        unsigned w1 = __byte_perm(__byte_perm(u[4], u[5], 0x0040),
                                  __byte_perm(u[6], u[7], 0x0040), 0x5410);
        *reinterpret_cast<uint2*>(&d_M[(size_t)(r0 + r) * NPTS + j0]) =
            make_uint2(w0, w1);
    }
}

// One power-iteration step via integer dp4a with in-block split-K:
// 8 warps = 4 row-pairs x 2 K-halves; u32 partials combined in smem (exact).
// x normalized+quantized to u16 (lo/hi u8 planes) in the prologue.
// M read via __ldcg (L2-cached, L1-bypassed) so x stays hot in L1.
__global__ void __launch_bounds__(256) k_gemv(int k) {
    const float* __restrict__ x = (k & 1) ? d_v1 : d_v0;
    float* __restrict__       y = (k & 1) ? d_v0 : d_v1;

    __shared__ unsigned sxlo[NPTS / 4];     // 1536 words
    __shared__ unsigned sxhi[NPTS / 4];
    __shared__ float red[8];
    __shared__ unsigned parts[2][8][2];     // [half][row-in-block][lo/hi]

    const int tid = threadIdx.x;
    const float4* xv = reinterpret_cast<const float4*>(x);

    float4 v[6];
    float ss = 0.0f;
#pragma unroll
    for (int t = 0; t < 6; t++) {
        v[t] = xv[tid + 256 * t];
        ss = fmaf(v[t].x, v[t].x, fmaf(v[t].y, v[t].y,
             fmaf(v[t].z, v[t].z, fmaf(v[t].w, v[t].w, ss))));
    }
#pragma unroll
    for (int o = 16; o; o >>= 1) ss += __shfl_xor_sync(0xffffffffu, ss, o);
    const int warp = tid >> 5, lane = tid & 31;
    if (lane == 0) red[warp] = ss;
    __syncthreads();
    ss = 0.0f;
#pragma unroll
    for (int w = 0; w < 8; w++) ss += red[w];

    const float inv = (k == 0) ? 1.0f : (1.0f / (sqrtf(ss) + 1e-6f));
    const float qs  = 65535.0f * inv;

#pragma unroll
    for (int t = 0; t < 6; t++) {
        unsigned q0 = __float2uint_rn(v[t].x * qs);
        unsigned q1 = __float2uint_rn(v[t].y * qs);
        unsigned q2 = __float2uint_rn(v[t].z * qs);
        unsigned q3 = __float2uint_rn(v[t].w * qs);
        const int f = tid + 256 * t;
        sxlo[f] = (q0 & 255u) | ((q1 & 255u) << 8) |
                  ((q2 & 255u) << 16) | ((q3 & 255u) << 24);
        sxhi[f] = (q0 >> 8) | ((q1 >> 8) << 8) |
                  ((q2 >> 8) << 16) | ((q3 >> 8) << 24);
    }
    __syncthreads();

    const int h  = warp >> 2;               // K-half
    const int rw = warp & 3;                // row-pair within block
    const int r0 = blockIdx.x * 8 + rw * 2;
    const uint4* M4  = reinterpret_cast<const uint4*>(d_M);
    const uint4* sl4 = reinterpret_cast<const uint4*>(sxlo);
    const uint4* sh4 = reinterpret_cast<const uint4*>(sxhi);
    const size_t rb = (size_t)r0 * (NPTS / 16);
    const int base = h * 192;

    unsigned lo0 = 0, hi0 = 0, lo1 = 0, hi1 = 0;
#pragma unroll
    for (int it = 0; it < 6; it++) {
        const int c = base + it * 32 + lane;   // 16-column chunk id
        uint4 xl = sl4[c];
        uint4 xh = sh4[c];
        uint4 m0 = __ldcg(&M4[rb + c]);
        uint4 m1 = __ldcg(&M4[rb + (NPTS / 16) + c]);
        lo0 = __dp4a(m0.x, xl.x, lo0); hi0 = __dp4a(m0.x, xh.x, hi0);
        lo0 = __dp4a(m0.y, xl.y, lo0); hi0 = __dp4a(m0.y, xh.y, hi0);
        lo0 = __dp4a(m0.z, xl.z, lo0); hi0 = __dp4a(m0.z, xh.z, hi0);
        lo0 = __dp4a(m0.w, xl.w, lo0); hi0 = __dp4a(m0.w, xh.w, hi0);
        lo1 = __dp4a(m1.x, xl.x, lo1); hi1 = __dp4a(m1.x, xh.x, hi1);
        lo1 = __dp4a(m1.y, xl.y, lo1); hi1 = __dp4a(m1.y, xh.y, hi1);
        lo1 = __dp4a(m1.z, xl.z, lo1); hi1 = __dp4a(m1.z, xh.z, hi1);
        lo1 = __dp4a(m1.w, xl.w, lo1); hi1 = __dp4a(m1.w, xh.w, hi1);
    }
#pragma unroll
    for (int o = 16; o; o >>= 1) {
        lo0 += __shfl_xor_sync(0xffffffffu, lo0, o);
        hi0 += __shfl_xor_sync(0xffffffffu, hi0, o);
        lo1 += __shfl_xor_sync(0xffffffffu, lo1, o);
        hi1 += __shfl_xor_sync(0xffffffffu, hi1, o);
    }
    if (lane == 0) {
        parts[h][rw * 2    ][0] = lo0;  parts[h][rw * 2    ][1] = hi0;
        parts[h][rw * 2 + 1][0] = lo1;  parts[h][rw * 2 + 1][1] = hi1;
    }
    __syncthreads();
    if (tid < 8) {
        const unsigned lo = parts[0][tid][0] + parts[1][tid][0];   // exact u32
        const unsigned hi = parts[0][tid][1] + parts[1][tid][1];
        const float outsc = 1.0f / (255.0f * 65535.0f);
        y[blockIdx.x * 8 + tid] = ((float)lo + 256.0f * (float)hi) * outsc;
    }
}

// Final normalization into d_out (last raw result in d_v0 after 10 iters).
__global__ void __launch_bounds__(256) k_final(float* __restrict__ out) {
    __shared__ float red[8];
    const int tid = threadIdx.x;
    float ss = 0.0f;
#pragma unroll
    for (int t = 0; t < 24; t++) {
        float v = d_v0[tid + 256 * t];
        ss = fmaf(v, v, ss);
    }
#pragma unroll
    for (int o = 16; o; o >>= 1) ss += __shfl_xor_sync(0xffffffffu, ss, o);
    if ((tid & 31) == 0) red[tid >> 5] = ss;
    __syncthreads();
    ss = 0.0f;
#pragma unroll
    for (int w = 0; w < 8; w++) ss += red[w];
    const float inv = 1.0f / (sqrtf(ss) + 1e-6f);
    const int i = blockIdx.x * 256 + tid;
    out[i] = d_v0[i] * inv;
}

extern "C" void kernel_launch(void* const* d_in, const int* in_sizes, int n_in,
                              void* d_out, int out_size) {
    const float* p2 = (const float*)d_in[0];  // ipts2d (N,2) fp32
    const float* p3 = (const float*)d_in[1];  // ipts3d (N,3) fp32

    k_init<<<24, 256>>>();
    dim3 bgrid(3, NPTS / 8);                  // 8x8 tile per thread
    k_build<<<bgrid, 256>>>(p2, p3);
    for (int k = 0; k < NITERS; k++)
        k_gemv<<<NPTS / 8, 256>>>(k);         // 768 blocks, 8 rows, split-K x2
    k_final<<<NPTS / 256, 256>>>((float*)d_out);
}

// round 5
// speedup vs baseline: 1.1395x; 1.1395x over previous
#include <cuda_runtime.h>

#define NPTS 6144
#define NITERS 10

// Scratch (static device globals — allocation-free per harness rules)
__device__ unsigned char d_M[(size_t)NPTS * NPTS];   // 37.7 MB u8 matrix, L2-resident
__device__ float d_v0[NPTS];
__device__ float d_v1[NPTS];

__device__ __forceinline__ float fsqrt_approx(float x) {
    float r;
    asm("sqrt.approx.f32 %0, %1;" : "=f"(r) : "f"(x));
    return r;
}

// ---- packed f32x2 helpers (sm_103a) ----
typedef unsigned long long u64t;
__device__ __forceinline__ u64t pk2(float lo, float hi) {
    u64t r; asm("mov.b64 %0, {%1, %2};" : "=l"(r) : "f"(lo), "f"(hi)); return r;
}
__device__ __forceinline__ void upk2(float& lo, float& hi, u64t v) {
    asm("mov.b64 {%0, %1}, %2;" : "=f"(lo), "=f"(hi) : "l"(v));
}
__device__ __forceinline__ u64t add2(u64t a, u64t b) {
    u64t r; asm("add.rn.f32x2 %0, %1, %2;" : "=l"(r) : "l"(a), "l"(b)); return r;
}
__device__ __forceinline__ u64t mul2(u64t a, u64t b) {
    u64t r; asm("mul.rn.f32x2 %0, %1, %2;" : "=l"(r) : "l"(a), "l"(b)); return r;
}
__device__ __forceinline__ u64t fma2(u64t a, u64t b, u64t c) {
    u64t r; asm("fma.rn.f32x2 %0, %1, %2, %3;" : "=l"(r) : "l"(a), "l"(b), "l"(c));
    return r;
}

// Build M in u8 fixed-point: q = round(255 * max(0, 1 - 100*cross^2)),
// cross^2 = a + b - 2*sqrt(a*b), a=|p2_i-p2_j|^2, b=|p3_i-p3_j|^2.
// Packed 2-wide via fma.rn.f32x2; 2^23 magic-add rounding in the last FMA.
// Block (0,0) also initializes d_v0 = ones (saves a launch).
__global__ void __launch_bounds__(256) k_build(const float* __restrict__ p2,
                                               const float* __restrict__ p3) {
    const int tid = threadIdx.x;
    if (blockIdx.x == 0 && blockIdx.y == 0) {
#pragma unroll
        for (int t = 0; t < NPTS / 256; t++) d_v0[tid + 256 * t] = 1.0f;
    }
    const int j0 = (blockIdx.x * 256 + tid) * 8;   // 8 cols
    const int r0 = blockIdx.y * 8;                 // 8 rows

    const float4* p2v = reinterpret_cast<const float4*>(p2);
    const float4* p3v = reinterpret_cast<const float4*>(p3);

    u64t ncx[4], ncy[4], n3x[4], n3y[4], n3z[4];
#pragma unroll
    for (int k = 0; k < 4; k++) {
        float4 a = __ldg(&p2v[j0 / 2 + k]);
        ncx[k] = pk2(-a.x, -a.z);
        ncy[k] = pk2(-a.y, -a.w);
    }
    {
        float q3[24];
#pragma unroll
        for (int k = 0; k < 6; k++) {
            float4 a = __ldg(&p3v[(3 * j0) / 4 + k]);
            q3[4*k] = a.x; q3[4*k+1] = a.y; q3[4*k+2] = a.z; q3[4*k+3] = a.w;
        }
#pragma unroll
        for (int k = 0; k < 4; k++) {
            n3x[k] = pk2(-q3[6*k],   -q3[6*k+3]);
            n3y[k] = pk2(-q3[6*k+1], -q3[6*k+4]);
            n3z[k] = pk2(-q3[6*k+2], -q3[6*k+5]);
        }
    }
    float rx[8], ry[8];
#pragma unroll
    for (int k = 0; k < 4; k++) {
        float4 a = __ldg(&p2v[r0 / 2 + k]);
        rx[2*k] = a.x; ry[2*k] = a.y; rx[2*k+1] = a.z; ry[2*k+1] = a.w;
    }
    float r3[24];
#pragma unroll
    for (int k = 0; k < 6; k++) {
        float4 a = __ldg(&p3v[(3 * r0) / 4 + k]);
        r3[4*k] = a.x; r3[4*k+1] = a.y; r3[4*k+2] = a.z; r3[4*k+3] = a.w;
    }

    const u64t NEG2  = pk2(-2.0f, -2.0f);
    const u64t NEGK  = pk2(-25500.0f, -25500.0f);
    const u64t MAGIC = pk2(8388863.0f, 8388863.0f);

#pragma unroll
    for (int r = 0; r < 8; r++) {
        const u64t sx2 = pk2(rx[r], rx[r]);
        const u64t sy2 = pk2(ry[r], ry[r]);
        const u64t sx3 = pk2(r3[3*r],   r3[3*r]);
        const u64t sy3 = pk2(r3[3*r+1], r3[3*r+1]);
        const u64t sz3 = pk2(r3[3*r+2], r3[3*r+2]);
        unsigned u[8];
#pragma unroll
        for (int p = 0; p < 4; p++) {
            u64t dx = add2(sx2, ncx[p]);
            u64t dy = add2(sy2, ncy[p]);
            u64t a  = fma2(dx, dx, mul2(dy, dy));
            u64t d0 = add2(sx3, n3x[p]);
            u64t d1 = add2(sy3, n3y[p]);
            u64t d2 = add2(sz3, n3z[p]);
            u64t b  = fma2(d2, d2, fma2(d1, d1, mul2(d0, d0)));
            u64t ab = mul2(a, b);
            u64t apb = add2(a, b);
            float ab0, ab1;
            upk2(ab0, ab1, ab);
            u64t s  = pk2(fsqrt_approx(ab0), fsqrt_approx(ab1));
            u64t cr = fma2(NEG2, s, apb);       // (sqrt a - sqrt b)^2
            u64t t  = fma2(NEGK, cr, MAGIC);    // 2^23 + 255 - 25500*cr
            float t0, t1;
            upk2(t0, t1, t);
            t0 = fminf(fmaxf(t0, 8388608.0f), 8388863.0f);
            t1 = fminf(fmaxf(t1, 8388608.0f), 8388863.0f);
            u[2*p]   = __float_as_uint(t0);     // byte = low 8 mantissa bits
            u[2*p+1] = __float_as_uint(t1);
        }
        unsigned w0 = __byte_perm(__byte_perm(u[0], u[1], 0x0040),
                                  __byte_perm(u[2], u[3], 0x0040), 0x5410);
        unsigned w1 = __byte_perm(__byte_perm(u[4], u[5], 0x0040),
                                  __byte_perm(u[6], u[7], 0x0040), 0x5410);
        *reinterpret_cast<uint2*>(&d_M[(size_t)(r0 + r) * NPTS + j0]) =
            make_uint2(w0, w1);
    }
}

// One power-iteration step via integer dp4a.
// 256 threads = 8 warps; each warp owns 2 full rows (12 K-iterations) ->
// 16 rows/block, grid 384. x staged once per block as u16 lo/hi u8 planes.
// M streamed with __ldcg (L2-only) so x float4 reads stay hot in L1.
__global__ void __launch_bounds__(256) k_gemv(int k) {
    const float* __restrict__ x = (k & 1) ? d_v1 : d_v0;
    float* __restrict__       y = (k & 1) ? d_v0 : d_v1;

    __shared__ unsigned sxlo[NPTS / 4];   // 1536 words, lo bytes of xq
    __shared__ unsigned sxhi[NPTS / 4];   // hi bytes
    __shared__ float red[8];

    const int tid = threadIdx.x;
    const float4* xv = reinterpret_cast<const float4*>(x);

    float4 v[6];
    float ss = 0.0f;
#pragma unroll
    for (int t = 0; t < 6; t++) {
        v[t] = xv[tid + 256 * t];
        ss = fmaf(v[t].x, v[t].x, fmaf(v[t].y, v[t].y,
             fmaf(v[t].z, v[t].z, fmaf(v[t].w, v[t].w, ss))));
    }
#pragma unroll
    for (int o = 16; o; o >>= 1) ss += __shfl_xor_sync(0xffffffffu, ss, o);
    const int warp = tid >> 5, lane = tid & 31;
    if (lane == 0) red[warp] = ss;
    __syncthreads();
    ss = 0.0f;
#pragma unroll
    for (int w = 0; w < 8; w++) ss += red[w];

    const float inv = (k == 0) ? 1.0f : (1.0f / (sqrtf(ss) + 1e-6f));
    const float qs  = 65535.0f * inv;

#pragma unroll
    for (int t = 0; t < 6; t++) {
        unsigned q0 = __float2uint_rn(v[t].x * qs);
        unsigned q1 = __float2uint_rn(v[t].y * qs);
        unsigned q2 = __float2uint_rn(v[t].z * qs);
        unsigned q3 = __float2uint_rn(v[t].w * qs);
        const int f = tid + 256 * t;
        sxlo[f] = (q0 & 255u) | ((q1 & 255u) << 8) |
                  ((q2 & 255u) << 16) | ((q3 & 255u) << 24);
        sxhi[f] = (q0 >> 8) | ((q1 >> 8) << 8) |
                  ((q2 >> 8) << 16) | ((q3 >> 8) << 24);
    }
    __syncthreads();

    const int r0 = blockIdx.x * 16 + warp * 2;
    const uint4* M4  = reinterpret_cast<const uint4*>(d_M);
    const uint4* sl4 = reinterpret_cast<const uint4*>(sxlo);
    const uint4* sh4 = reinterpret_cast<const uint4*>(sxhi);
    const size_t rb = (size_t)r0 * (NPTS / 16);

    unsigned lo0 = 0, hi0 = 0, lo1 = 0, hi1 = 0;
#pragma unroll
    for (int it = 0; it < 12; it++) {
        const int c = it * 32 + lane;     // 16-column chunk id
        uint4 xl = sl4[c];
        uint4 xh = sh4[c];
        uint4 m0 = __ldcg(&M4[rb + c]);
        uint4 m1 = __ldcg(&M4[rb + (NPTS / 16) + c]);
        lo0 = __dp4a(m0.x, xl.x, lo0); hi0 = __dp4a(m0.x, xh.x, hi0);
        lo0 = __dp4a(m0.y, xl.y, lo0); hi0 = __dp4a(m0.y, xh.y, hi0);
        lo0 = __dp4a(m0.z, xl.z, lo0); hi0 = __dp4a(m0.z, xh.z, hi0);
        lo0 = __dp4a(m0.w, xl.w, lo0); hi0 = __dp4a(m0.w, xh.w, hi0);
        lo1 = __dp4a(m1.x, xl.x, lo1); hi1 = __dp4a(m1.x, xh.x, hi1);
        lo1 = __dp4a(m1.y, xl.y, lo1); hi1 = __dp4a(m1.y, xh.y, hi1);
        lo1 = __dp4a(m1.z, xl.z, lo1); hi1 = __dp4a(m1.z, xh.z, hi1);
        lo1 = __dp4a(m1.w, xl.w, lo1); hi1 = __dp4a(m1.w, xh.w, hi1);
    }
#pragma unroll
    for (int o = 16; o; o >>= 1) {
        lo0 += __shfl_xor_sync(0xffffffffu, lo0, o);
        hi0 += __shfl_xor_sync(0xffffffffu, hi0, o);
        lo1 += __shfl_xor_sync(0xffffffffu, lo1, o);
        hi1 += __shfl_xor_sync(0xffffffffu, hi1, o);
    }
    if (lane == 0) {
        const float outsc = 1.0f / (255.0f * 65535.0f);
        y[r0    ] = ((float)lo0 + 256.0f * (float)hi0) * outsc;
        y[r0 + 1] = ((float)lo1 + 256.0f * (float)hi1) * outsc;
    }
}

// Final normalization into d_out (last raw result in d_v0 after 10 iters).
__global__ void __launch_bounds__(256) k_final(float* __restrict__ out) {
    __shared__ float red[8];
    const int tid = threadIdx.x;
    float ss = 0.0f;
#pragma unroll
    for (int t = 0; t < 24; t++) {
        float v = d_v0[tid + 256 * t];
        ss = fmaf(v, v, ss);
    }
#pragma unroll
    for (int o = 16; o; o >>= 1) ss += __shfl_xor_sync(0xffffffffu, ss, o);
    if ((tid & 31) == 0) red[tid >> 5] = ss;
    __syncthreads();
    ss = 0.0f;
#pragma unroll
    for (int w = 0; w < 8; w++) ss += red[w];
    const float inv = 1.0f / (sqrtf(ss) + 1e-6f);
    const int i = blockIdx.x * 256 + tid;
    out[i] = d_v0[i] * inv;
}

extern "C" void kernel_launch(void* const* d_in, const int* in_sizes, int n_in,
                              void* d_out, int out_size) {
    const float* p2 = (const float*)d_in[0];  // ipts2d (N,2) fp32
    const float* p3 = (const float*)d_in[1];  // ipts3d (N,3) fp32

    dim3 bgrid(3, NPTS / 8);                  // 8x8 tile per thread
    k_build<<<bgrid, 256>>>(p2, p3);
    for (int k = 0; k < NITERS; k++)
        k_gemv<<<NPTS / 16, 256>>>(k);        // 384 blocks, 16 rows each
    k_final<<<NPTS / 256, 256>>>((float*)d_out);
}